// round 5
// baseline (speedup 1.0000x reference)
#include <cuda_runtime.h>
#include <cstddef>

// x: (256, 3, 256, 256) fp32, z_where: (256, 4) fp32, inverse: int scalar
// out: (256, 3, 64, 64) fp32
static constexpr int B    = 256;
static constexpr int C    = 3;
static constexpr int HIN  = 256;
static constexpr int WIN  = 256;
static constexpr int HOUT = 64;
static constexpr int WOUT = 64;

static constexpr int ROWS_PER_CTA = 4;   // output rows per CTA
static constexpr int RMAX = 14;          // max input rows needed: 12*sy + 2, sy < 1
static constexpr int WPAD = 260;         // max input cols needed: 252*sx + 2 <= 254, padded

__device__ __forceinline__ float map_iy(int oy, float sy, float ty) {
    float ys = (2.0f * (float)oy + 1.0f) * (1.0f / (float)HOUT) - 1.0f;
    float v  = sy * ys + ty;
    return ((v + 1.0f) * (float)HIN - 1.0f) * 0.5f;
}
__device__ __forceinline__ float map_ix(int ox, float sx, float tx) {
    float xs = (2.0f * (float)ox + 1.0f) * (1.0f / (float)WOUT) - 1.0f;
    float u  = sx * xs + tx;
    return ((u + 1.0f) * (float)WIN - 1.0f) * 0.5f;
}

__global__ __launch_bounds__(256) void st_kernel(
    const float* __restrict__ x,
    const float* __restrict__ zw,
    const int*   __restrict__ inv,
    float* __restrict__ out)
{
    __shared__ float sm[C][RMAX][WPAD];

    const int b       = blockIdx.x;
    const int base_oy = blockIdx.y * ROWS_PER_CTA;
    const int tid     = threadIdx.x;

    float sx = __ldg(zw + b * 4 + 0);
    float sy = __ldg(zw + b * 4 + 1);
    float tx = __ldg(zw + b * 4 + 2);
    float ty = __ldg(zw + b * 4 + 3);
    const int invv = __ldg(inv);

    if (invv) {
        float isx = 1.0f / (sx + 1e-6f);
        float isy = 1.0f / (sy + 1e-6f);
        tx = -tx * isx;  ty = -ty * isy;
        sx = isx;        sy = isy;
    }

    const int oy = base_oy + (tid >> 6);
    const int ox = tid & 63;

    if (!invv) {
        // ---- window bounds for this CTA (sx, sy in [0,1) => monotone, bounded) ----
        const float iy_first = map_iy(base_oy, sy, ty);
        const float iy_last  = map_iy(base_oy + ROWS_PER_CTA - 1, sy, ty);
        const int y_lo = (int)floorf(iy_first);
        const int y_hi = (int)floorf(iy_last) + 1;
        int R = y_hi - y_lo + 1;
        if (R > RMAX) R = RMAX;  // provably <= 14; defensive

        const float ix_first = map_ix(0, sx, tx);
        const float ix_last  = map_ix(WOUT - 1, sx, tx);
        const int x_lo = (int)floorf(ix_first);
        const int x_hi = (int)floorf(ix_last) + 1;
        int W = x_hi - x_lo + 1;
        if (W > WPAD - 4) W = WPAD - 4;  // provably <= 254; defensive

        // ---- stage the window, fully coalesced ----
        const int wid  = tid >> 5;
        const int lane = tid & 31;
        const size_t base_in = (size_t)b * C * HIN * WIN;
#pragma unroll
        for (int c = 0; c < C; c++) {
            const float* xc = x + base_in + (size_t)c * HIN * WIN;
            for (int r = wid; r < R; r += 8) {
                const int gy = min(max(y_lo + r, 0), HIN - 1);
                const float* rowp = xc + gy * WIN;
                for (int col = lane; col < W; col += 32) {
                    const int gx = min(max(x_lo + col, 0), WIN - 1);
                    sm[c][r][col] = __ldg(rowp + gx);
                }
            }
        }
        __syncthreads();

        // ---- per-pixel bilinear from smem ----
        const float iy = map_iy(oy, sy, ty);
        const float ix = map_ix(ox, sx, tx);
        const float fy0 = floorf(iy), fx0 = floorf(ix);
        const int y0 = (int)fy0, y1 = y0 + 1;
        const int x0 = (int)fx0, x1 = x0 + 1;
        const float wy1 = iy - fy0, wy0 = 1.0f - wy1;
        const float wx1 = ix - fx0, wx0 = 1.0f - wx1;
        const bool vy0 = (y0 >= 0) & (y0 < HIN);
        const bool vy1 = (y1 >= 0) & (y1 < HIN);
        const bool vx0 = (x0 >= 0) & (x0 < WIN);
        const bool vx1 = (x1 >= 0) & (x1 < WIN);
        const float w00 = (vy0 & vx0) ? wy0 * wx0 : 0.0f;
        const float w01 = (vy0 & vx1) ? wy0 * wx1 : 0.0f;
        const float w10 = (vy1 & vx0) ? wy1 * wx0 : 0.0f;
        const float w11 = (vy1 & vx1) ? wy1 * wx1 : 0.0f;

        int r0 = y0 - y_lo;           // in [0, R-1)
        int c0 = x0 - x_lo;           // in [0, W-1)
        r0 = min(max(r0, 0), RMAX - 2);
        c0 = min(max(c0, 0), WPAD - 2);

        const size_t base_out = (size_t)b * C * HOUT * WOUT + (size_t)oy * WOUT + ox;
#pragma unroll
        for (int c = 0; c < C; c++) {
            const float v00 = sm[c][r0][c0];
            const float v01 = sm[c][r0][c0 + 1];
            const float v10 = sm[c][r0 + 1][c0];
            const float v11 = sm[c][r0 + 1][c0 + 1];
            out[base_out + (size_t)c * HOUT * WOUT] =
                fmaf(v00, w00, fmaf(v01, w01, fmaf(v10, w10, v11 * w11)));
        }
    } else {
        // ---- fallback: direct global gather (inverse path, scales unbounded) ----
        const float iy = map_iy(oy, sy, ty);
        const float ix = map_ix(ox, sx, tx);
        const float fy0 = floorf(iy), fx0 = floorf(ix);
        const int y0 = (int)fy0, y1 = y0 + 1;
        const int x0 = (int)fx0, x1 = x0 + 1;
        const float wy1 = iy - fy0, wy0 = 1.0f - wy1;
        const float wx1 = ix - fx0, wx0 = 1.0f - wx1;
        const bool vy0 = (y0 >= 0) & (y0 < HIN);
        const bool vy1 = (y1 >= 0) & (y1 < HIN);
        const bool vx0 = (x0 >= 0) & (x0 < WIN);
        const bool vx1 = (x1 >= 0) & (x1 < WIN);
        const int y0c = min(max(y0, 0), HIN - 1);
        const int y1c = min(max(y1, 0), HIN - 1);
        const int x0c = min(max(x0, 0), WIN - 1);
        const int x1c = min(max(x1, 0), WIN - 1);
        const float w00 = (vy0 & vx0) ? wy0 * wx0 : 0.0f;
        const float w01 = (vy0 & vx1) ? wy0 * wx1 : 0.0f;
        const float w10 = (vy1 & vx0) ? wy1 * wx0 : 0.0f;
        const float w11 = (vy1 & vx1) ? wy1 * wx1 : 0.0f;

        const size_t base_in  = (size_t)b * C * HIN * WIN;
        const size_t base_out = (size_t)b * C * HOUT * WOUT + (size_t)oy * WOUT + ox;
        const int o00 = y0c * WIN + x0c, o01 = y0c * WIN + x1c;
        const int o10 = y1c * WIN + x0c, o11 = y1c * WIN + x1c;
#pragma unroll
        for (int c = 0; c < C; c++) {
            const float* xc = x + base_in + (size_t)c * HIN * WIN;
            out[base_out + (size_t)c * HOUT * WOUT] =
                fmaf(__ldg(xc + o00), w00,
                fmaf(__ldg(xc + o01), w01,
                fmaf(__ldg(xc + o10), w10, __ldg(xc + o11) * w11)));
        }
    }
}

extern "C" void kernel_launch(void* const* d_in, const int* in_sizes, int n_in,
                              void* d_out, int out_size)
{
    const float* x   = (const float*)d_in[0];
    const float* zw  = (const float*)d_in[1];
    const int*   inv = (const int*)d_in[2];
    float* out = (float*)d_out;

    dim3 grid(B, HOUT / ROWS_PER_CTA);
    dim3 block(256);
    st_kernel<<<grid, block>>>(x, zw, inv, out);
}

// round 6
// speedup vs baseline: 1.6250x; 1.6250x over previous
#include <cuda_runtime.h>
#include <cstddef>

// x: (256, 3, 256, 256) fp32, z_where: (256, 4) fp32, inverse: int scalar
// out: (256, 3, 64, 64) fp32
static constexpr int B    = 256;
static constexpr int C    = 3;
static constexpr int HIN  = 256;
static constexpr int WIN  = 256;
static constexpr int HOUT = 64;
static constexpr int WOUT = 64;

static constexpr int BUFW = 144;   // floats per staged row (span<=132), 16B-mult
static constexpr int NVMAX = BUFW / 4;

__device__ __forceinline__ float map_iy(int oy, float sy, float ty) {
    float ys = (2.0f * (float)oy + 1.0f) * (1.0f / (float)HOUT) - 1.0f;
    float v  = sy * ys + ty;
    return ((v + 1.0f) * (float)HIN - 1.0f) * 0.5f;
}
__device__ __forceinline__ float map_ix(int ox, float sx, float tx) {
    float xs = (2.0f * (float)ox + 1.0f) * (1.0f / (float)WOUT) - 1.0f;
    float u  = sx * xs + tx;
    return ((u + 1.0f) * (float)WIN - 1.0f) * 0.5f;
}

__global__ __launch_bounds__(256) void st_kernel(
    const float* __restrict__ x,
    const float* __restrict__ zw,
    const int*   __restrict__ inv,
    float* __restrict__ out)
{
    __shared__ float buf[8][2][BUFW];

    const int b    = blockIdx.x;
    const int w    = threadIdx.x >> 5;
    const int lane = threadIdx.x & 31;
    const int h    = blockIdx.y * 8 + w;   // half-row id 0..127
    const int oy   = h >> 1;
    const int ox_base = (h & 1) << 5;
    const int ox   = ox_base + lane;

    float sx = __ldg(zw + b * 4 + 0);
    float sy = __ldg(zw + b * 4 + 1);
    float tx = __ldg(zw + b * 4 + 2);
    float ty = __ldg(zw + b * 4 + 3);
    const int invv = __ldg(inv);

    if (invv) {
        float isx = 1.0f / (sx + 1e-6f);
        float isy = 1.0f / (sy + 1e-6f);
        tx = -tx * isx;  ty = -ty * isy;
        sx = isx;        sy = isy;
    }

    // ---- y side (uniform across warp) ----
    const float iy = map_iy(oy, sy, ty);
    const float fy0 = floorf(iy);
    const int y0 = (int)fy0, y1 = y0 + 1;
    const float wy1 = iy - fy0, wy0 = 1.0f - wy1;
    const bool vy0 = (y0 >= 0) & (y0 < HIN);
    const bool vy1 = (y1 >= 0) & (y1 < HIN);
    const int y0c = min(max(y0, 0), HIN - 1);
    const int y1c = min(max(y1, 0), HIN - 1);

    // ---- x side (per lane) ----
    const float ix = map_ix(ox, sx, tx);
    const float fx0 = floorf(ix);
    const int x0 = (int)fx0;
    const float wx1 = ix - fx0, wx0 = 1.0f - wx1;
    const bool vx0 = (x0 >= 0) & (x0 < WIN);
    const bool vx1 = (x0 + 1 >= 0) & (x0 + 1 < WIN);
    const float w00 = (vy0 & vx0) ? wy0 * wx0 : 0.0f;
    const float w01 = (vy0 & vx1) ? wy0 * wx1 : 0.0f;
    const float w10 = (vy1 & vx0) ? wy1 * wx0 : 0.0f;
    const float w11 = (vy1 & vx1) ? wy1 * wx1 : 0.0f;

    const size_t base_in  = (size_t)b * C * HIN * WIN;
    const size_t base_out = (size_t)b * C * HOUT * WOUT + (size_t)oy * WOUT + ox;

    if (!invv) {
        // warp-uniform staging window: sx >= 0 -> ix monotone in ox
        const int x_lo = (int)floorf(map_ix(ox_base, sx, tx));
        const int x_hi = (int)floorf(map_ix(ox_base + 31, sx, tx)) + 1;
        const int xl = max(x_lo, 0);
        const int xh = min(x_hi, WIN - 1);

        if (xl > xh) {
            // entire warp window outside image in x -> all weights zero
#pragma unroll
            for (int c = 0; c < C; c++)
                out[base_out + (size_t)c * HOUT * WOUT] = 0.0f;
            return;
        }

        const int xa = xl & ~3;                       // 16B-aligned start
        int nv = (xh - xa + 4) >> 2;                  // float4 count covering xh
        nv = min(nv, NVMAX);                          // defensive (smem safety)
        const int last = 4 * nv - 1;
        const int c0 = min(max(x0 - xa, 0), last);
        const int c1 = min(max(x0 + 1 - xa, 0), last);

#pragma unroll
        for (int c = 0; c < C; c++) {
            const float* xc  = x + base_in + (size_t)c * HIN * WIN;
            const float* r0p = xc + y0c * WIN;
            const float* r1p = xc + y1c * WIN;

            __syncwarp();
            const int total = 2 * nv;
            for (int j = lane; j < total; j += 32) {
                const int rrow = (j >= nv) ? 1 : 0;
                const int jj   = rrow ? j - nv : j;
                const float* rp = rrow ? r1p : r0p;
                const int g = xa + 4 * jj;
                float4 v;
                if (g + 3 < WIN) {
                    v = *reinterpret_cast<const float4*>(rp + g);
                } else {
                    v.x = rp[min(g,     WIN - 1)];
                    v.y = rp[min(g + 1, WIN - 1)];
                    v.z = rp[min(g + 2, WIN - 1)];
                    v.w = rp[min(g + 3, WIN - 1)];
                }
                *reinterpret_cast<float4*>(&buf[w][rrow][4 * jj]) = v;
            }
            __syncwarp();

            const float v00 = buf[w][0][c0];
            const float v01 = buf[w][0][c1];
            const float v10 = buf[w][1][c0];
            const float v11 = buf[w][1][c1];
            out[base_out + (size_t)c * HOUT * WOUT] =
                fmaf(v00, w00, fmaf(v01, w01, fmaf(v10, w10, v11 * w11)));
        }
    } else {
        // inverse path: scales unbounded -> direct global gather
        const int x0c = min(max(x0, 0), WIN - 1);
        const int x1c = min(max(x0 + 1, 0), WIN - 1);
        const int o00 = y0c * WIN + x0c, o01 = y0c * WIN + x1c;
        const int o10 = y1c * WIN + x0c, o11 = y1c * WIN + x1c;
#pragma unroll
        for (int c = 0; c < C; c++) {
            const float* xc = x + base_in + (size_t)c * HIN * WIN;
            out[base_out + (size_t)c * HOUT * WOUT] =
                fmaf(__ldg(xc + o00), w00,
                fmaf(__ldg(xc + o01), w01,
                fmaf(__ldg(xc + o10), w10, __ldg(xc + o11) * w11)));
        }
    }
}

extern "C" void kernel_launch(void* const* d_in, const int* in_sizes, int n_in,
                              void* d_out, int out_size)
{
    const float* x   = (const float*)d_in[0];
    const float* zw  = (const float*)d_in[1];
    const int*   inv = (const int*)d_in[2];
    float* out = (float*)d_out;

    dim3 grid(B, 16);
    dim3 block(256);
    st_kernel<<<grid, block>>>(x, zw, inv, out);
}

// round 7
// speedup vs baseline: 1.8220x; 1.1212x over previous
#include <cuda_runtime.h>
#include <cstddef>

// x: (256, 3, 256, 256) fp32, z_where: (256, 4) fp32, inverse: int scalar
// out: (256, 3, 64, 64) fp32
static constexpr int B    = 256;
static constexpr int C    = 3;
static constexpr int HIN  = 256;
static constexpr int WIN  = 256;
static constexpr int HOUT = 64;
static constexpr int WOUT = 64;

static constexpr int BUFW = 136;  // staged floats per row: span<=129 (+pad)

__device__ __forceinline__ float map_iy(int oy, float sy, float ty) {
    float ys = (2.0f * (float)oy + 1.0f) * (1.0f / (float)HOUT) - 1.0f;
    float v  = sy * ys + ty;
    return ((v + 1.0f) * (float)HIN - 1.0f) * 0.5f;
}
__device__ __forceinline__ float map_ix(int ox, float sx, float tx) {
    float xs = (2.0f * (float)ox + 1.0f) * (1.0f / (float)WOUT) - 1.0f;
    float u  = sx * xs + tx;
    return ((u + 1.0f) * (float)WIN - 1.0f) * 0.5f;
}

// Load float4 at row[g..g+3], clamping the (rare) tail that would step past
// the image row range to stay inside the tensor.
__device__ __forceinline__ float4 ld_f4_safe(const float* __restrict__ rp, int g) {
    if (g + 3 < WIN) {
        return *reinterpret_cast<const float4*>(rp + g);
    } else {
        float4 v;
        v.x = rp[min(g,     WIN - 1)];
        v.y = rp[min(g + 1, WIN - 1)];
        v.z = rp[min(g + 2, WIN - 1)];
        v.w = rp[min(g + 3, WIN - 1)];
        return v;
    }
}

__global__ __launch_bounds__(256, 4) void st_kernel(
    const float* __restrict__ x,
    const float* __restrict__ zw,
    const int*   __restrict__ inv,
    float* __restrict__ out)
{
    __shared__ float buf[8][C][2][BUFW];   // 26112 B

    const int b    = blockIdx.x;
    const int w    = threadIdx.x >> 5;
    const int lane = threadIdx.x & 31;
    const int h    = blockIdx.y * 8 + w;   // half-row id 0..127
    const int oy   = h >> 1;
    const int ox_base = (h & 1) << 5;
    const int ox   = ox_base + lane;

    float sx = __ldg(zw + b * 4 + 0);
    float sy = __ldg(zw + b * 4 + 1);
    float tx = __ldg(zw + b * 4 + 2);
    float ty = __ldg(zw + b * 4 + 3);
    const int invv = __ldg(inv);

    if (invv) {
        float isx = 1.0f / (sx + 1e-6f);
        float isy = 1.0f / (sy + 1e-6f);
        tx = -tx * isx;  ty = -ty * isy;
        sx = isx;        sy = isy;
    }

    // ---- y side (uniform across warp) ----
    const float iy = map_iy(oy, sy, ty);
    const float fy0 = floorf(iy);
    const int y0 = (int)fy0, y1 = y0 + 1;
    const float wy1 = iy - fy0, wy0 = 1.0f - wy1;
    const bool vy0 = (y0 >= 0) & (y0 < HIN);
    const bool vy1 = (y1 >= 0) & (y1 < HIN);
    const int y0c = min(max(y0, 0), HIN - 1);
    const int y1c = min(max(y1, 0), HIN - 1);

    // ---- x side (per lane) ----
    const float ix = map_ix(ox, sx, tx);
    const float fx0 = floorf(ix);
    const int x0 = (int)fx0;
    const float wx1 = ix - fx0, wx0 = 1.0f - wx1;
    const bool vx0 = (x0 >= 0) & (x0 < WIN);
    const bool vx1 = (x0 + 1 >= 0) & (x0 + 1 < WIN);
    const float w00 = (vy0 & vx0) ? wy0 * wx0 : 0.0f;
    const float w01 = (vy0 & vx1) ? wy0 * wx1 : 0.0f;
    const float w10 = (vy1 & vx0) ? wy1 * wx0 : 0.0f;
    const float w11 = (vy1 & vx1) ? wy1 * wx1 : 0.0f;

    const size_t base_in  = (size_t)b * C * HIN * WIN;
    const size_t base_out = (size_t)b * C * HOUT * WOUT + (size_t)oy * WOUT + ox;

    if (!invv) {
        // warp-uniform staging window (sx >= 0 on forward path -> monotone ix)
        const int x_lo = (int)floorf(map_ix(ox_base, sx, tx));
        const int x_hi = (int)floorf(map_ix(ox_base + 31, sx, tx)) + 1;

        if (x_hi < 0 || x_lo > WIN - 1) {
            // whole warp window outside image in x -> all weights zero
#pragma unroll
            for (int c = 0; c < C; c++)
                out[base_out + (size_t)c * HOUT * WOUT] = 0.0f;
            return;
        }

        const int xl   = max(x_lo, 0);
        const int xh   = min(x_hi, WIN - 1);
        const int xa   = xl & ~3;                 // 16B-aligned start
        const int span = xh - xa;                 // provably <= 129 for sx < 1
        const int g    = xa + 4 * lane;
        const bool pmain  = (g <= xh);
        const bool pextra = (lane == 0) & (span >= 125);  // 33rd float4

        // ---- stage all channels, all rows: deep LDG.128 MLP ----
#pragma unroll
        for (int c = 0; c < C; c++) {
            const float* xc  = x + base_in + (size_t)c * HIN * WIN;
            const float* r0p = xc + y0c * WIN;
            const float* r1p = xc + y1c * WIN;
            if (pmain) {
                *reinterpret_cast<float4*>(&buf[w][c][0][4 * lane]) = ld_f4_safe(r0p, g);
                *reinterpret_cast<float4*>(&buf[w][c][1][4 * lane]) = ld_f4_safe(r1p, g);
            }
            if (pextra) {
                *reinterpret_cast<float4*>(&buf[w][c][0][128]) = ld_f4_safe(r0p, xa + 128);
                *reinterpret_cast<float4*>(&buf[w][c][1][128]) = ld_f4_safe(r1p, xa + 128);
            }
        }
        __syncwarp();

        // ---- sample from smem ----
        const int hi = min(span, BUFW - 4) + 3;   // highest staged slot
        const int c0 = min(max(x0 - xa, 0), hi);
        const int c1 = min(max(x0 + 1 - xa, 0), hi);

#pragma unroll
        for (int c = 0; c < C; c++) {
            const float v00 = buf[w][c][0][c0];
            const float v01 = buf[w][c][0][c1];
            const float v10 = buf[w][c][1][c0];
            const float v11 = buf[w][c][1][c1];
            out[base_out + (size_t)c * HOUT * WOUT] =
                fmaf(v00, w00, fmaf(v01, w01, fmaf(v10, w10, v11 * w11)));
        }
    } else {
        // inverse path: scales unbounded -> direct global gather
        const int x0c = min(max(x0, 0), WIN - 1);
        const int x1c = min(max(x0 + 1, 0), WIN - 1);
        const int o00 = y0c * WIN + x0c, o01 = y0c * WIN + x1c;
        const int o10 = y1c * WIN + x0c, o11 = y1c * WIN + x1c;
#pragma unroll
        for (int c = 0; c < C; c++) {
            const float* xc = x + base_in + (size_t)c * HIN * WIN;
            out[base_out + (size_t)c * HOUT * WOUT] =
                fmaf(__ldg(xc + o00), w00,
                fmaf(__ldg(xc + o01), w01,
                fmaf(__ldg(xc + o10), w10, __ldg(xc + o11) * w11)));
        }
    }
}

extern "C" void kernel_launch(void* const* d_in, const int* in_sizes, int n_in,
                              void* d_out, int out_size)
{
    const float* x   = (const float*)d_in[0];
    const float* zw  = (const float*)d_in[1];
    const int*   inv = (const int*)d_in[2];
    float* out = (float*)d_out;

    dim3 grid(B, 16);
    dim3 block(256);
    st_kernel<<<grid, block>>>(x, zw, inv, out);
}

// round 8
// speedup vs baseline: 2.4922x; 1.3679x over previous
#include <cuda_runtime.h>
#include <cstddef>

// x: (256, 3, 256, 256) fp32, z_where: (256, 4) fp32, inverse: int scalar
// out: (256, 3, 64, 64) fp32
static constexpr int B    = 256;
static constexpr int C    = 3;
static constexpr int HIN  = 256;
static constexpr int WIN  = 256;
static constexpr int HOUT = 64;
static constexpr int WOUT = 64;

__global__ __launch_bounds__(256) void st_kernel(
    const float* __restrict__ x,
    const float* __restrict__ zw,
    const int*   __restrict__ inv,
    float* __restrict__ out)
{
    const int b   = blockIdx.x;
    const int tid = threadIdx.x;
    const int oy  = blockIdx.y * 4 + (tid >> 6);
    const int ox  = tid & 63;

    float sx = __ldg(zw + b * 4 + 0);
    float sy = __ldg(zw + b * 4 + 1);
    float tx = __ldg(zw + b * 4 + 2);
    float ty = __ldg(zw + b * 4 + 3);

    if (__ldg(inv)) {
        float isx = 1.0f / (sx + 1e-6f);
        float isy = 1.0f / (sy + 1e-6f);
        tx = -tx * isx;
        ty = -ty * isy;
        sx = isx;
        sy = isy;
    }

    // grid coords
    const float xs = (2.0f * (float)ox + 1.0f) * (1.0f / (float)WOUT) - 1.0f;
    const float ys = (2.0f * (float)oy + 1.0f) * (1.0f / (float)HOUT) - 1.0f;
    const float u = sx * xs + tx;
    const float v = sy * ys + ty;
    const float ix = ((u + 1.0f) * (float)WIN - 1.0f) * 0.5f;
    const float iy = ((v + 1.0f) * (float)HIN - 1.0f) * 0.5f;

    const float fx0 = floorf(ix);
    const float fy0 = floorf(iy);
    const int x0 = (int)fx0, x1 = x0 + 1;
    const int y0 = (int)fy0, y1 = y0 + 1;

    const float wx1 = ix - fx0, wx0 = 1.0f - wx1;
    const float wy1 = iy - fy0, wy0 = 1.0f - wy1;

    const bool vx0 = (x0 >= 0) & (x0 < WIN);
    const bool vx1 = (x1 >= 0) & (x1 < WIN);
    const bool vy0 = (y0 >= 0) & (y0 < HIN);
    const bool vy1 = (y1 >= 0) & (y1 < HIN);

    const int y0c = min(max(y0, 0), HIN - 1);
    const int y1c = min(max(y1, 0), HIN - 1);

    const float w00 = (vy0 & vx0) ? wy0 * wx0 : 0.0f;
    const float w01 = (vy0 & vx1) ? wy0 * wx1 : 0.0f;
    const float w10 = (vy1 & vx0) ? wy1 * wx0 : 0.0f;
    const float w11 = (vy1 & vx1) ? wy1 * wx1 : 0.0f;

    // 16B-aligned float4 window covering taps x0, x0+1 (up to alignment crossing)
    const int xb = min(max(x0 & ~3, 0), WIN - 4);
    const int d0 = x0 - xb;
    const bool needx = (d0 == 3);                 // tap x1 crosses the float4
    const int s0 = min(max(d0, 0), 3);
    const int x1c = min(max(x1, 0), WIN - 1);     // safe addr for crossing load

    // selector predicates (shared across channels)
    const bool p1 = (s0 >= 1), p2 = (s0 >= 2), p3 = (s0 >= 3);

    const size_t base_in  = (size_t)b * C * HIN * WIN;
    const size_t base_out = (size_t)b * C * HOUT * WOUT + (size_t)oy * WOUT + ox;

#pragma unroll
    for (int c = 0; c < C; c++) {
        const float* xc  = x + base_in + (size_t)c * HIN * WIN;
        const float* r0p = xc + y0c * WIN;
        const float* r1p = xc + y1c * WIN;

        const float4 q0 = *reinterpret_cast<const float4*>(r0p + xb);
        const float4 q1 = *reinterpret_cast<const float4*>(r1p + xb);
        float e0 = 0.0f, e1 = 0.0f;
        if (needx) {                               // rare predicated fixup
            e0 = __ldg(r0p + x1c);
            e1 = __ldg(r1p + x1c);
        }

        // v00 = q0[s0], v01 = q0[s0+1] (or e0 if crossing); same for row1
        const float v00 = p3 ? q0.w : (p2 ? q0.z : (p1 ? q0.y : q0.x));
        const float v01 = p3 ? e0   : (p2 ? q0.w : (p1 ? q0.z : q0.y));
        const float v10 = p3 ? q1.w : (p2 ? q1.z : (p1 ? q1.y : q1.x));
        const float v11 = p3 ? e1   : (p2 ? q1.w : (p1 ? q1.z : q1.y));

        out[base_out + (size_t)c * HOUT * WOUT] =
            fmaf(v00, w00, fmaf(v01, w01, fmaf(v10, w10, v11 * w11)));
    }
}

extern "C" void kernel_launch(void* const* d_in, const int* in_sizes, int n_in,
                              void* d_out, int out_size)
{
    const float* x   = (const float*)d_in[0];
    const float* zw  = (const float*)d_in[1];
    const int*   inv = (const int*)d_in[2];
    float* out = (float*)d_out;

    dim3 grid(B, HOUT / 4);
    dim3 block(256);
    st_kernel<<<grid, block>>>(x, zw, inv, out);
}

// round 9
// speedup vs baseline: 2.8047x; 1.1254x over previous
#include <cuda_runtime.h>
#include <cstddef>

// x: (256, 3, 256, 256) fp32, z_where: (256, 4) fp32, inverse: int scalar
// out: (256, 3, 64, 64) fp32
static constexpr int B    = 256;
static constexpr int C    = 3;
static constexpr int HIN  = 256;
static constexpr int WIN  = 256;
static constexpr int HOUT = 64;
static constexpr int WOUT = 64;

static constexpr int YQ = 16;   // y-quads (4 rows each)
static constexpr int BG = 37;   // batch groups; 16*37 = 592 CTAs = 1 wave
static constexpr int GRID = YQ * BG;

__global__ __launch_bounds__(256) void st_kernel(
    const float* __restrict__ x,
    const float* __restrict__ zw,
    const int*   __restrict__ inv,
    float* __restrict__ out)
{
    const int cta = blockIdx.x;
    const int yq  = cta & 15;        // 0..15
    const int bg  = cta >> 4;        // 0..36
    const int tid = threadIdx.x;
    const int oy  = yq * 4 + (tid >> 6);
    const int ox  = tid & 63;

    const int invv = __ldg(inv);

    // grid coords (fixed per thread across all batches)
    const float xs = (2.0f * (float)ox + 1.0f) * (1.0f / (float)WOUT) - 1.0f;
    const float ys = (2.0f * (float)oy + 1.0f) * (1.0f / (float)HOUT) - 1.0f;
    const size_t out_pix = (size_t)oy * WOUT + ox;

    for (int b = bg; b < B; b += BG) {
        float sx = __ldg(zw + b * 4 + 0);
        float sy = __ldg(zw + b * 4 + 1);
        float tx = __ldg(zw + b * 4 + 2);
        float ty = __ldg(zw + b * 4 + 3);

        if (invv) {
            float isx = 1.0f / (sx + 1e-6f);
            float isy = 1.0f / (sy + 1e-6f);
            tx = -tx * isx;
            ty = -ty * isy;
            sx = isx;
            sy = isy;
        }

        const float u = sx * xs + tx;
        const float v = sy * ys + ty;
        const float ix = ((u + 1.0f) * (float)WIN - 1.0f) * 0.5f;
        const float iy = ((v + 1.0f) * (float)HIN - 1.0f) * 0.5f;

        const float fx0 = floorf(ix);
        const float fy0 = floorf(iy);
        const int x0 = (int)fx0, x1 = x0 + 1;
        const int y0 = (int)fy0, y1 = y0 + 1;

        const float wx1 = ix - fx0, wx0 = 1.0f - wx1;
        const float wy1 = iy - fy0, wy0 = 1.0f - wy1;

        const bool vx0 = (x0 >= 0) & (x0 < WIN);
        const bool vx1 = (x1 >= 0) & (x1 < WIN);
        const bool vy0 = (y0 >= 0) & (y0 < HIN);
        const bool vy1 = (y1 >= 0) & (y1 < HIN);

        const int x0c = min(max(x0, 0), WIN - 1);
        const int x1c = min(max(x1, 0), WIN - 1);
        const int y0c = min(max(y0, 0), HIN - 1);
        const int y1c = min(max(y1, 0), HIN - 1);

        const float w00 = (vy0 & vx0) ? wy0 * wx0 : 0.0f;
        const float w01 = (vy0 & vx1) ? wy0 * wx1 : 0.0f;
        const float w10 = (vy1 & vx0) ? wy1 * wx0 : 0.0f;
        const float w11 = (vy1 & vx1) ? wy1 * wx1 : 0.0f;

        const size_t base_in  = (size_t)b * C * HIN * WIN;
        const size_t base_out = (size_t)b * C * HOUT * WOUT + out_pix;
        const int o00 = y0c * WIN + x0c;
        const int o01 = y0c * WIN + x1c;
        const int o10 = y1c * WIN + x0c;
        const int o11 = y1c * WIN + x1c;

#pragma unroll
        for (int c = 0; c < C; c++) {
            const float* xc = x + base_in + (size_t)c * HIN * WIN;
            float v00 = __ldg(xc + o00);
            float v01 = __ldg(xc + o01);
            float v10 = __ldg(xc + o10);
            float v11 = __ldg(xc + o11);
            out[base_out + (size_t)c * HOUT * WOUT] =
                fmaf(v00, w00, fmaf(v01, w01, fmaf(v10, w10, v11 * w11)));
        }
    }
}

extern "C" void kernel_launch(void* const* d_in, const int* in_sizes, int n_in,
                              void* d_out, int out_size)
{
    const float* x   = (const float*)d_in[0];
    const float* zw  = (const float*)d_in[1];
    const int*   inv = (const int*)d_in[2];
    float* out = (float*)d_out;

    st_kernel<<<GRID, 256>>>(x, zw, inv, out);
}